// round 14
// baseline (speedup 1.0000x reference)
#include <cuda_runtime.h>
#include <cuda_fp16.h>
#include <cstdint>
#include <math.h>

// Problem dims (fixed)
#define BATCH 2048
#define TT    20
#define CD    512
#define HD    1024
#define VD    2048
#define QD    1024
#define KCAT  (CD + HD)     // 1536
#define N4    (4 * HD)      // 4096

// ---------------- fp32 scratch (rank-sorted / time-major layouts) -------------
__device__ float g_fv   [BATCH * CD];
__device__ float g_fq   [BATCH * CD];
__device__ float g_fvq  [BATCH * CD];
__device__ float g_h1   [BATCH * CD];
__device__ float g_h2   [BATCH * HD];
__device__ float g_y    [(size_t)TT * BATCH * HD];
__device__ float g_b2cat[N4];

// ---------------- fp16 scratch --------------------------------------------------
__device__ __half g_gi1a [(size_t)TT * BATCH * 3 * CD];  // time-major sorted
__device__ __half g_gh1  [BATCH * 3 * CD];
__device__ __half g_comb [(size_t)BATCH * N4];           // per-step combined gates
__device__ __half g_c16s [(size_t)TT * BATCH * CD];
__device__ __half g_v16s [BATCH * VD];
__device__ __half g_q16s [BATCH * QD];
__device__ __half g_wih1h[3 * CD * CD];
__device__ __half g_whh1h[3 * CD * CD];
__device__ __half g_w2cat[(size_t)N4 * KCAT];            // concatenated GRU2 weights
__device__ __half g_wvh  [CD * VD];
__device__ __half g_wqh  [CD * QD];
__device__ __half g_wfch [HD * HD];
__device__ __half g_h1h  [BATCH * CD];
__device__ __half g_h2h  [BATCH * HD];
__device__ __half g_atta [(size_t)TT * BATCH * CD];
__device__ __half g_h2ah [(size_t)TT * BATCH * HD];

// ---------------- sorting metadata ----------------------------------------------
__device__ int g_perm [BATCH];
__device__ int g_rank [BATCH];
__device__ int g_mt   [TT];

// ---------------- helpers --------------------------------------------------------
__device__ __forceinline__ float sigmf(float x) { return 1.0f / (1.0f + expf(-x)); }
__device__ __forceinline__ float leakyf(float x) { return x > 0.0f ? x : 0.01f * x; }

__device__ __forceinline__ void mma_f16(
    float& c0, float& c1, float& c2, float& c3,
    uint32_t a0, uint32_t a1, uint32_t a2, uint32_t a3,
    uint32_t b0, uint32_t b1)
{
    asm volatile(
        "mma.sync.aligned.m16n8k16.row.col.f32.f16.f16.f32 "
        "{%0,%1,%2,%3}, {%4,%5,%6,%7}, {%8,%9}, {%0,%1,%2,%3};"
        : "+f"(c0), "+f"(c1), "+f"(c2), "+f"(c3)
        : "r"(a0), "r"(a1), "r"(a2), "r"(a3), "r"(b0), "r"(b1));
}

__device__ __forceinline__ void ldm_x4(uint32_t& r0, uint32_t& r1, uint32_t& r2, uint32_t& r3,
                                       uint32_t saddr)
{
    asm volatile("ldmatrix.sync.aligned.m8n8.x4.shared.b16 {%0,%1,%2,%3}, [%4];"
                 : "=r"(r0), "=r"(r1), "=r"(r2), "=r"(r3) : "r"(saddr));
}

__device__ __forceinline__ void cp16(uint32_t saddr, const void* gptr) {
    asm volatile("cp.async.cg.shared.global [%0], [%1], 16;" :: "r"(saddr), "l"(gptr));
}
__device__ __forceinline__ void cp_commit() { asm volatile("cp.async.commit_group;"); }
__device__ __forceinline__ void cp_wait3()  { asm volatile("cp.async.wait_group 3;"); }

__device__ __forceinline__ void store2(float* p, float v0, float v1) {
    *(float2*)p = make_float2(v0, v1);
}
__device__ __forceinline__ void store2(__half* p, float v0, float v1) {
    *(__half2*)p = __floats2half2_rn(v0, v1);
}

// ================= fp16 GEMM engine, 128x128 tile =================
#define LDSH 40
#define TILEB (128 * LDSH * 2)
#define STAGEB_P (2 * TILEB)
#define NSTG 5
#define SMEM_P (NSTG * STAGEB_P)     // 102400 bytes

template<typename OT>
__global__ __launch_bounds__(256, 2) void h16_gemm_nt(
    const __half* __restrict__ A, const __half* __restrict__ B,
    const float* __restrict__ bias, OT* __restrict__ C,
    int M, int N, int K, int epi,
    const int* __restrict__ mlim, int tsel, int tmaj)
{
    extern __shared__ __align__(16) char smem[];
    const int bm = blockIdx.y * 128;
    const int bn = blockIdx.x * 128;

    if (mlim) {
        if (tmaj) {
            if ((bm & 2047) >= mlim[bm >> 11]) return;
        } else {
            if (bm >= mlim[tsel]) return;
        }
    }

    const int tid  = threadIdx.x;
    const int wid  = tid >> 5;
    const int lane = tid & 31;
    const int wm   = wid >> 1;
    const int wn   = wid & 1;
    const int g    = lane >> 2;
    const int t    = lane & 3;

    const __half* Ag = A + (size_t)bm * K;
    const __half* Bg = B + (size_t)bn * K;
    const uint32_t sbase = (uint32_t)__cvta_generic_to_shared(smem);

    const int r0s = tid >> 2, v0s = tid & 3;
    const int r1s = (tid + 256) >> 2, v1s = tid & 3;

    const uint32_t a_off = (uint32_t)(((lane & 15) * LDSH + (lane >> 4) * 8) * 2);
    const int b_row = ((lane >> 4) << 3) + (lane & 7);
    const uint32_t b_koff = (uint32_t)((((lane >> 3) & 1) * 8) * 2);

    float acc[2][8][4];
#pragma unroll
    for (int i = 0; i < 2; i++)
#pragma unroll
        for (int j = 0; j < 8; j++)
#pragma unroll
            for (int r = 0; r < 4; r++) acc[i][j][r] = 0.0f;

    const int NKC = K >> 5;

    auto issue = [&](int kc) {
        const int st = kc % NSTG;
        const uint32_t sa = sbase + st * STAGEB_P;
        const uint32_t sb = sa + TILEB;
        const uint32_t o0 = (uint32_t)((r0s * LDSH + v0s * 8) * 2);
        const uint32_t o1 = (uint32_t)((r1s * LDSH + v1s * 8) * 2);
        cp16(sa + o0, Ag + (size_t)r0s * K + kc * 32 + v0s * 8);
        cp16(sb + o0, Bg + (size_t)r0s * K + kc * 32 + v0s * 8);
        cp16(sa + o1, Ag + (size_t)r1s * K + kc * 32 + v1s * 8);
        cp16(sb + o1, Bg + (size_t)r1s * K + kc * 32 + v1s * 8);
        cp_commit();
    };

    issue(0); issue(1); issue(2); issue(3);

    for (int kc = 0; kc < NKC; kc++) {
        cp_wait3();
        __syncthreads();
        const int st = kc % NSTG;
        const uint32_t cAb = sbase + st * STAGEB_P;
        const uint32_t cBb = cAb + TILEB;
#pragma unroll
        for (int ks = 0; ks < 2; ks++) {
            const uint32_t kso = (uint32_t)(ks * 16 * 2);
            uint32_t af[2][4];
#pragma unroll
            for (int mt = 0; mt < 2; mt++) {
                const uint32_t addr = cAb + (uint32_t)((wm * 32 + mt * 16) * LDSH * 2)
                                     + a_off + kso;
                ldm_x4(af[mt][0], af[mt][1], af[mt][2], af[mt][3], addr);
            }
            uint32_t bf[8][2];
#pragma unroll
            for (int p = 0; p < 4; p++) {
                const uint32_t addr = cBb
                    + (uint32_t)(((wn * 64 + p * 16 + b_row) * LDSH) * 2)
                    + kso + b_koff;
                ldm_x4(bf[2 * p][0], bf[2 * p][1], bf[2 * p + 1][0], bf[2 * p + 1][1], addr);
            }
#pragma unroll
            for (int mt = 0; mt < 2; mt++)
#pragma unroll
                for (int nt = 0; nt < 8; nt++)
                    mma_f16(acc[mt][nt][0], acc[mt][nt][1],
                            acc[mt][nt][2], acc[mt][nt][3],
                            af[mt][0], af[mt][1], af[mt][2], af[mt][3],
                            bf[nt][0], bf[nt][1]);
        }
        const int nxt = kc + 4;
        if (nxt < NKC) issue(nxt);
    }

#pragma unroll
    for (int mt = 0; mt < 2; mt++) {
        const int r0 = bm + wm * 32 + mt * 16 + g;
#pragma unroll
        for (int nt = 0; nt < 8; nt++) {
            const int col = bn + wn * 64 + nt * 8 + 2 * t;
            float b0 = 0.0f, b1 = 0.0f;
            if (bias) { b0 = bias[col]; b1 = bias[col + 1]; }
            float v0 = acc[mt][nt][0] + b0;
            float v1 = acc[mt][nt][1] + b1;
            float v2 = acc[mt][nt][2] + b0;
            float v3 = acc[mt][nt][3] + b1;
            if (epi == 1) { v0 = leakyf(v0); v1 = leakyf(v1); v2 = leakyf(v2); v3 = leakyf(v3); }
            store2(C + (size_t)r0 * N + col, v0, v1);
            store2(C + (size_t)(r0 + 8) * N + col, v2, v3);
        }
    }
}

// ================= concat-A GEMM: C = [A1|A2] @ W2cat^T + b2cat ==================
// A1 = atta(t) [B, CD], A2 = h2h [B, HD]; K = 1536, N = 4096, output fp16.
// Chunks 0..15 read A1, chunks 16..47 read A2. Early-exit on mlim[tsel].
__global__ __launch_bounds__(256, 2) void h16_gemm_cat(
    const __half* __restrict__ A1, const __half* __restrict__ A2,
    const __half* __restrict__ B,
    const float* __restrict__ bias, __half* __restrict__ C,
    const int* __restrict__ mlim, int tsel)
{
    extern __shared__ __align__(16) char smem[];
    const int bm = blockIdx.y * 128;
    const int bn = blockIdx.x * 128;
    if (bm >= mlim[tsel]) return;

    const int tid  = threadIdx.x;
    const int wid  = tid >> 5;
    const int lane = tid & 31;
    const int wm   = wid >> 1;
    const int wn   = wid & 1;
    const int g    = lane >> 2;
    const int t    = lane & 3;

    const __half* Bg = B + (size_t)bn * KCAT;
    const uint32_t sbase = (uint32_t)__cvta_generic_to_shared(smem);

    const int r0s = tid >> 2, v0s = tid & 3;
    const int r1s = (tid + 256) >> 2, v1s = tid & 3;

    const uint32_t a_off = (uint32_t)(((lane & 15) * LDSH + (lane >> 4) * 8) * 2);
    const int b_row = ((lane >> 4) << 3) + (lane & 7);
    const uint32_t b_koff = (uint32_t)((((lane >> 3) & 1) * 8) * 2);

    float acc[2][8][4];
#pragma unroll
    for (int i = 0; i < 2; i++)
#pragma unroll
        for (int j = 0; j < 8; j++)
#pragma unroll
            for (int r = 0; r < 4; r++) acc[i][j][r] = 0.0f;

    const int NKC = KCAT >> 5;    // 48

    auto aptr = [&](int row, int kc, int v) -> const __half* {
        if (kc < (CD >> 5))
            return A1 + (size_t)(bm + row) * CD + kc * 32 + v * 8;
        return A2 + (size_t)(bm + row) * HD + (kc - (CD >> 5)) * 32 + v * 8;
    };

    auto issue = [&](int kc) {
        const int st = kc % NSTG;
        const uint32_t sa = sbase + st * STAGEB_P;
        const uint32_t sb = sa + TILEB;
        const uint32_t o0 = (uint32_t)((r0s * LDSH + v0s * 8) * 2);
        const uint32_t o1 = (uint32_t)((r1s * LDSH + v1s * 8) * 2);
        cp16(sa + o0, aptr(r0s, kc, v0s));
        cp16(sb + o0, Bg + (size_t)r0s * KCAT + kc * 32 + v0s * 8);
        cp16(sa + o1, aptr(r1s, kc, v1s));
        cp16(sb + o1, Bg + (size_t)r1s * KCAT + kc * 32 + v1s * 8);
        cp_commit();
    };

    issue(0); issue(1); issue(2); issue(3);

    for (int kc = 0; kc < NKC; kc++) {
        cp_wait3();
        __syncthreads();
        const int st = kc % NSTG;
        const uint32_t cAb = sbase + st * STAGEB_P;
        const uint32_t cBb = cAb + TILEB;
#pragma unroll
        for (int ks = 0; ks < 2; ks++) {
            const uint32_t kso = (uint32_t)(ks * 16 * 2);
            uint32_t af[2][4];
#pragma unroll
            for (int mt = 0; mt < 2; mt++) {
                const uint32_t addr = cAb + (uint32_t)((wm * 32 + mt * 16) * LDSH * 2)
                                     + a_off + kso;
                ldm_x4(af[mt][0], af[mt][1], af[mt][2], af[mt][3], addr);
            }
            uint32_t bf[8][2];
#pragma unroll
            for (int p = 0; p < 4; p++) {
                const uint32_t addr = cBb
                    + (uint32_t)(((wn * 64 + p * 16 + b_row) * LDSH) * 2)
                    + kso + b_koff;
                ldm_x4(bf[2 * p][0], bf[2 * p][1], bf[2 * p + 1][0], bf[2 * p + 1][1], addr);
            }
#pragma unroll
            for (int mt = 0; mt < 2; mt++)
#pragma unroll
                for (int nt = 0; nt < 8; nt++)
                    mma_f16(acc[mt][nt][0], acc[mt][nt][1],
                            acc[mt][nt][2], acc[mt][nt][3],
                            af[mt][0], af[mt][1], af[mt][2], af[mt][3],
                            bf[nt][0], bf[nt][1]);
        }
        const int nxt = kc + 4;
        if (nxt < NKC) issue(nxt);
    }

#pragma unroll
    for (int mt = 0; mt < 2; mt++) {
        const int r0 = bm + wm * 32 + mt * 16 + g;
#pragma unroll
        for (int nt = 0; nt < 8; nt++) {
            const int col = bn + wn * 64 + nt * 8 + 2 * t;
            float b0 = bias[col], b1 = bias[col + 1];
            store2(C + (size_t)r0 * N4 + col, acc[mt][nt][0] + b0, acc[mt][nt][1] + b1);
            store2(C + (size_t)(r0 + 8) * N4 + col, acc[mt][nt][2] + b0, acc[mt][nt][3] + b1);
        }
    }
}

// ---------------- prep kernels -----------------------------------------------------
__global__ void w2cat_kernel(const float* __restrict__ wih2, const float* __restrict__ whh2,
                             __half* __restrict__ o)
{
    size_t idx = (size_t)blockIdx.x * blockDim.x + threadIdx.x;
    if (idx >= (size_t)N4 * KCAT) return;
    int c = (int)(idx / KCAT);
    int k = (int)(idx - (size_t)c * KCAT);
    float val = 0.0f;
    if (c < 2 * HD) {                 // r-sum, z-sum rows
        val = (k < CD) ? wih2[(size_t)c * CD + k]
                       : whh2[(size_t)c * HD + (k - CD)];
    } else if (c < 3 * HD) {          // gi_n: atta part only
        int cn = 2 * HD + (c - 2 * HD);
        if (k < CD) val = wih2[(size_t)cn * CD + k];
    } else {                          // gh_n: h2 part only
        int cn = 2 * HD + (c - 3 * HD);
        if (k >= CD) val = whh2[(size_t)cn * HD + (k - CD)];
    }
    o[idx] = __float2half(val);
}

__global__ void b2cat_kernel(const float* __restrict__ bih2, const float* __restrict__ bhh2,
                             float* __restrict__ o)
{
    int c = blockIdx.x * blockDim.x + threadIdx.x;
    if (c >= N4) return;
    if (c < 2 * HD)      o[c] = bih2[c] + bhh2[c];
    else if (c < 3 * HD) o[c] = bih2[2 * HD + (c - 2 * HD)];
    else                 o[c] = bhh2[2 * HD + (c - 3 * HD)];
}

// ---------------- sorting / permutation kernels ----------------------------------
__global__ void rank_kernel(const int* __restrict__ len,
                            int* __restrict__ perm, int* __restrict__ rankof)
{
    __shared__ int sl[BATCH];
    const int tid = threadIdx.x;
    for (int i = tid; i < BATCH; i += 1024) sl[i] = len[i];
    __syncthreads();
    for (int b = tid; b < BATCH; b += 1024) {
        const int lb = sl[b];
        int rk = 0;
        for (int b2 = 0; b2 < BATCH; b2++) {
            const int l2 = sl[b2];
            rk += (l2 > lb) || (l2 == lb && b2 < b);
        }
        perm[rk] = b;
        rankof[b] = rk;
    }
}

__global__ void mt_kernel(const int* __restrict__ len, int* __restrict__ mt) {
    const int t = threadIdx.x;
    if (t >= TT) return;
    int c = 0;
    for (int b = 0; b < BATCH; b++) c += (len[b] > t);
    mt[t] = c;
}

__global__ void f2h_kernel(const float* __restrict__ src, __half* __restrict__ dst, int n) {
    int i = (blockIdx.x * blockDim.x + threadIdx.x) * 4;
    if (i < n) {
        float4 f = *(const float4*)(src + i);
        *(__half2*)(dst + i)     = __floats2half2_rn(f.x, f.y);
        *(__half2*)(dst + i + 2) = __floats2half2_rn(f.z, f.w);
    }
}

__global__ void f2h_perm_kernel(const float* __restrict__ src, __half* __restrict__ dst,
                                const int* __restrict__ perm, int rowlen, int nrows)
{
    int idx = blockIdx.x * blockDim.x + threadIdx.x;
    const int vpr = rowlen / 4;
    if (idx >= nrows * vpr) return;
    const int r = idx / vpr, v = idx - r * vpr;
    const int b = perm[r];
    float4 f = *(const float4*)(src + (size_t)b * rowlen + v * 4);
    __half* d = dst + (size_t)r * rowlen + v * 4;
    *(__half2*)(d)     = __floats2half2_rn(f.x, f.y);
    *(__half2*)(d + 2) = __floats2half2_rn(f.z, f.w);
}

__global__ void permcap_kernel(const float* __restrict__ cap, __half* __restrict__ dst,
                               const int* __restrict__ perm)
{
    int idx = blockIdx.x * blockDim.x + threadIdx.x;
    const int vpr = CD / 4;
    if (idx >= TT * BATCH * vpr) return;
    const int v = idx % vpr;
    const int row = idx / vpr;
    const int r = row & (BATCH - 1);
    const int t = row >> 11;
    const int b = perm[r];
    float4 f = *(const float4*)(cap + ((size_t)b * TT + t) * CD + v * 4);
    __half* d = dst + (size_t)row * CD + v * 4;
    *(__half2*)(d)     = __floats2half2_rn(f.x, f.y);
    *(__half2*)(d + 2) = __floats2half2_rn(f.z, f.w);
}

__global__ void zero_state_kernel(float* __restrict__ f, __half* __restrict__ h, int n) {
    int i = blockIdx.x * blockDim.x + threadIdx.x;
    if (i < n) { f[i] = 0.0f; h[i] = __float2half(0.0f); }
}

__global__ void add_kernel(const float* __restrict__ a, const float* __restrict__ b,
                           float* __restrict__ c, int n) {
    int i = blockIdx.x * blockDim.x + threadIdx.x;
    if (i < n) c[i] = a[i] + b[i];
}

// ---------------- packed GRU elementwise kernels -----------------------------------
__global__ void gru1_att_sorted(
    const __half* __restrict__ gi1a,
    const __half* __restrict__ gh1,
    const float* __restrict__ caption,
    const float* __restrict__ fvqs,
    const int*   __restrict__ perm,
    const int*   __restrict__ mt,
    float* __restrict__ h1, __half* __restrict__ h1h,
    __half* __restrict__ atta,
    float* __restrict__ alphas,
    int t)
{
    int idx = blockIdx.x * blockDim.x + threadIdx.x;
    if (idx >= BATCH * (CD / 2)) return;
    const int r = idx / (CD / 2);
    const int j = (idx - r * (CD / 2)) * 2;
    const int b = perm[r];
    float* alp = alphas + ((size_t)b * TT + t) * CD + j;

    if (r >= mt[t]) {
        *(float2*)alp = make_float2(0.0f, 0.0f);
        return;
    }

    const __half* gi = gi1a + ((size_t)t * BATCH + r) * (3 * CD);
    const __half* gh = gh1 + (size_t)r * (3 * CD);

    float2 hv = *(float2*)(h1 + (size_t)r * CD + j);
    float2 gir = __half22float2(*(const __half2*)(gi + j));
    float2 giz = __half22float2(*(const __half2*)(gi + CD + j));
    float2 gin = __half22float2(*(const __half2*)(gi + 2 * CD + j));
    float2 ghr = __half22float2(*(const __half2*)(gh + j));
    float2 ghz = __half22float2(*(const __half2*)(gh + CD + j));
    float2 ghn = __half22float2(*(const __half2*)(gh + 2 * CD + j));

    float r0 = sigmf(gir.x + ghr.x), r1 = sigmf(gir.y + ghr.y);
    float z0 = sigmf(giz.x + ghz.x), z1 = sigmf(giz.y + ghz.y);
    float n0 = tanhf(gin.x + r0 * ghn.x), n1 = tanhf(gin.y + r1 * ghn.y);
    float h0 = (1.0f - z0) * n0 + z0 * hv.x;
    float h1v = (1.0f - z1) * n1 + z1 * hv.y;

    *(float2*)(h1 + (size_t)r * CD + j) = make_float2(h0, h1v);
    *(__half2*)(h1h + (size_t)r * CD + j) = __floats2half2_rn(h0, h1v);

    float2 x = *(const float2*)(caption + ((size_t)b * TT + t) * CD + j);
    float2 fq = *(const float2*)(fvqs + (size_t)r * CD + j);
    float a0 = sigmf(h0 * fq.x) * x.x;
    float a1 = sigmf(h1v * fq.y) * x.y;
    *(__half2*)(atta + ((size_t)t * BATCH + r) * CD + j) = __floats2half2_rn(a0, a1);
    *(float2*)alp = make_float2(a0, a1);
}

// GRU2 cell from combined gates: r=sig(c0), z=sig(c1), n=tanh(c2 + r*c3)
__global__ void gru2_comb(
    const __half* __restrict__ comb,    // [B, 4HD]
    const int*   __restrict__ mt,
    float* __restrict__ h2, __half* __restrict__ h2h,
    __half* __restrict__ h2ah,
    int t)
{
    int idx = blockIdx.x * blockDim.x + threadIdx.x;
    if (idx >= BATCH * (HD / 2)) return;
    const int r = idx / (HD / 2);
    const int j = (idx - r * (HD / 2)) * 2;
    if (r >= mt[t]) return;

    const __half* c = comb + (size_t)r * N4;
    float2 hv = *(float2*)(h2 + (size_t)r * HD + j);
    float2 c0 = __half22float2(*(const __half2*)(c + j));
    float2 c1 = __half22float2(*(const __half2*)(c + HD + j));
    float2 c2 = __half22float2(*(const __half2*)(c + 2 * HD + j));
    float2 c3 = __half22float2(*(const __half2*)(c + 3 * HD + j));

    float r0 = sigmf(c0.x), r1 = sigmf(c0.y);
    float z0 = sigmf(c1.x), z1 = sigmf(c1.y);
    float n0 = tanhf(c2.x + r0 * c3.x), n1 = tanhf(c2.y + r1 * c3.y);
    float h0 = (1.0f - z0) * n0 + z0 * hv.x;
    float h1v = (1.0f - z1) * n1 + z1 * hv.y;

    *(float2*)(h2 + (size_t)r * HD + j) = make_float2(h0, h1v);
    __half2 hh = __floats2half2_rn(h0, h1v);
    *(__half2*)(h2h + (size_t)r * HD + j) = hh;
    *(__half2*)(h2ah + ((size_t)t * BATCH + r) * HD + j) = hh;
}

__global__ void maxreduce_out(
    const float* __restrict__ y,
    const int*   __restrict__ cap_len,
    const int*   __restrict__ rankof,
    float* __restrict__ out)
{
    int idx = blockIdx.x * blockDim.x + threadIdx.x;
    if (idx >= BATCH * HD) return;
    const int b = idx / HD, j = idx - b * HD;
    const int len = cap_len[b];
    const int r = rankof[b];
    float m = 0.0f;
    for (int t = 0; t < len; t++)
        m = fmaxf(m, leakyf(y[((size_t)t * BATCH + r) * HD + j]));
    out[idx] = m;
}

// ---------------- launch ------------------------------------------------------------
static inline dim3 gemm_grid(int M, int N) { return dim3(N / 128, M / 128); }

extern "C" void kernel_launch(void* const* d_in, const int* in_sizes, int n_in,
                              void* d_out, int out_size)
{
    const float* v       = (const float*)d_in[0];
    const float* q       = (const float*)d_in[1];
    const float* caption = (const float*)d_in[2];
    const int*   cap_len = (const int*)  d_in[3];
    const float* w_ih1   = (const float*)d_in[4];
    const float* w_hh1   = (const float*)d_in[5];
    const float* b_ih1   = (const float*)d_in[6];
    const float* b_hh1   = (const float*)d_in[7];
    const float* w_ih2   = (const float*)d_in[8];
    const float* w_hh2   = (const float*)d_in[9];
    const float* b_ih2   = (const float*)d_in[10];
    const float* b_hh2   = (const float*)d_in[11];
    const float* Wv      = (const float*)d_in[12];
    const float* Wq      = (const float*)d_in[13];
    const float* Wfc     = (const float*)d_in[14];

    float* out    = (float*)d_out;
    float* alphas = (float*)d_out + (size_t)BATCH * HD;

    float *fv, *fq, *fvq, *h1, *h2, *y, *b2cat;
    cudaGetSymbolAddress((void**)&fv,    g_fv);
    cudaGetSymbolAddress((void**)&fq,    g_fq);
    cudaGetSymbolAddress((void**)&fvq,   g_fvq);
    cudaGetSymbolAddress((void**)&h1,    g_h1);
    cudaGetSymbolAddress((void**)&h2,    g_h2);
    cudaGetSymbolAddress((void**)&y,     g_y);
    cudaGetSymbolAddress((void**)&b2cat, g_b2cat);

    __half *gi1a, *gh1, *comb, *w2cat;
    __half *c16s, *v16s, *q16s, *wih1h, *whh1h, *wvh, *wqh, *wfch;
    __half *h1h, *h2h, *atta, *h2ah;
    cudaGetSymbolAddress((void**)&gi1a,  g_gi1a);
    cudaGetSymbolAddress((void**)&gh1,   g_gh1);
    cudaGetSymbolAddress((void**)&comb,  g_comb);
    cudaGetSymbolAddress((void**)&w2cat, g_w2cat);
    cudaGetSymbolAddress((void**)&c16s,  g_c16s);
    cudaGetSymbolAddress((void**)&v16s,  g_v16s);
    cudaGetSymbolAddress((void**)&q16s,  g_q16s);
    cudaGetSymbolAddress((void**)&wih1h, g_wih1h);
    cudaGetSymbolAddress((void**)&whh1h, g_whh1h);
    cudaGetSymbolAddress((void**)&wvh,   g_wvh);
    cudaGetSymbolAddress((void**)&wqh,   g_wqh);
    cudaGetSymbolAddress((void**)&wfch,  g_wfch);
    cudaGetSymbolAddress((void**)&h1h,   g_h1h);
    cudaGetSymbolAddress((void**)&h2h,   g_h2h);
    cudaGetSymbolAddress((void**)&atta,  g_atta);
    cudaGetSymbolAddress((void**)&h2ah,  g_h2ah);

    int *perm, *rankof, *mt;
    cudaGetSymbolAddress((void**)&perm,   g_perm);
    cudaGetSymbolAddress((void**)&rankof, g_rank);
    cudaGetSymbolAddress((void**)&mt,     g_mt);

    cudaFuncSetAttribute(h16_gemm_nt<float>,
                         cudaFuncAttributeMaxDynamicSharedMemorySize, SMEM_P);
    cudaFuncSetAttribute(h16_gemm_nt<__half>,
                         cudaFuncAttributeMaxDynamicSharedMemorySize, SMEM_P);
    cudaFuncSetAttribute(h16_gemm_cat,
                         cudaFuncAttributeMaxDynamicSharedMemorySize, SMEM_P);

    // ---- one-time stream/event creation ----
    static cudaStream_t s1 = nullptr, s2 = nullptr;
    static cudaEvent_t ePre, eGi1, eW2, eWf, evA[TT], evC[TT];
    if (!s1) {
        int loPri, hiPri;
        cudaDeviceGetStreamPriorityRange(&loPri, &hiPri);
        cudaStreamCreateWithPriority(&s1, cudaStreamNonBlocking, hiPri);
        cudaStreamCreateWithPriority(&s2, cudaStreamNonBlocking, hiPri);
        cudaEventCreateWithFlags(&ePre, cudaEventDisableTiming);
        cudaEventCreateWithFlags(&eGi1, cudaEventDisableTiming);
        cudaEventCreateWithFlags(&eW2,  cudaEventDisableTiming);
        cudaEventCreateWithFlags(&eWf,  cudaEventDisableTiming);
        for (int i = 0; i < TT; i++) {
            cudaEventCreateWithFlags(&evA[i], cudaEventDisableTiming);
            cudaEventCreateWithFlags(&evC[i], cudaEventDisableTiming);
        }
    }

    const int EW = 256;

    // =================== shared prefix on main: sort metadata =====================
    rank_kernel<<<1, 1024>>>(cap_len, perm, rankof);
    mt_kernel<<<1, 32>>>(cap_len, mt);
    cudaEventRecord(ePre, 0);
    cudaStreamWaitEvent(s1, ePre, 0);
    cudaStreamWaitEvent(s2, ePre, 0);

    // =================== main: critical prefix feeding h1 chain ===================
    f2h_kernel<<<(3 * CD * CD / 4 + EW - 1) / EW, EW>>>(w_ih1, wih1h, 3 * CD * CD);
    permcap_kernel<<<(TT * BATCH * (CD / 4) + EW - 1) / EW, EW>>>(caption, c16s, perm);
    h16_gemm_nt<__half><<<gemm_grid(TT * BATCH, 3 * CD), 256, SMEM_P>>>(
        c16s, wih1h, b_ih1, gi1a, TT * BATCH, 3 * CD, CD, 0, mt, 0, 1);
    cudaEventRecord(eGi1, 0);

    // =================== s1: fvq chain + h1-state init + whh1 cvt =================
    f2h_kernel<<<(3 * CD * CD / 4 + EW - 1) / EW, EW, 0, s1>>>(w_hh1, whh1h, 3 * CD * CD);
    f2h_kernel<<<(CD * VD / 4 + EW - 1) / EW, EW, 0, s1>>>(Wv, wvh, CD * VD);
    f2h_kernel<<<(CD * QD / 4 + EW - 1) / EW, EW, 0, s1>>>(Wq, wqh, CD * QD);
    f2h_perm_kernel<<<(BATCH * (VD / 4) + EW - 1) / EW, EW, 0, s1>>>(v, v16s, perm, VD, BATCH);
    f2h_perm_kernel<<<(BATCH * (QD / 4) + EW - 1) / EW, EW, 0, s1>>>(q, q16s, perm, QD, BATCH);
    h16_gemm_nt<float><<<gemm_grid(BATCH, CD), 256, SMEM_P, s1>>>(
        v16s, wvh, nullptr, fv, BATCH, CD, VD, 1, nullptr, 0, 0);
    h16_gemm_nt<float><<<gemm_grid(BATCH, CD), 256, SMEM_P, s1>>>(
        q16s, wqh, nullptr, fq, BATCH, CD, QD, 1, nullptr, 0, 0);
    add_kernel<<<(BATCH * CD + EW - 1) / EW, EW, 0, s1>>>(fv, fq, fvq, BATCH * CD);
    zero_state_kernel<<<(BATCH * CD + EW - 1) / EW, EW, 0, s1>>>(h1, h1h, BATCH * CD);

    // =================== s2: concat-weight build + Wfc cvt + h2 init ==============
    {
        size_t nw = (size_t)N4 * KCAT;
        w2cat_kernel<<<(unsigned)((nw + EW - 1) / EW), EW, 0, s2>>>(w_ih2, w_hh2, w2cat);
        b2cat_kernel<<<(N4 + EW - 1) / EW, EW, 0, s2>>>(b_ih2, b_hh2, b2cat);
        cudaEventRecord(eW2, s2);
        f2h_kernel<<<(HD * HD / 4 + EW - 1) / EW, EW, 0, s2>>>(Wfc, wfch, HD * HD);
        cudaEventRecord(eWf, s2);
        zero_state_kernel<<<(BATCH * HD + EW - 1) / EW, EW, 0, s2>>>(h2, h2h, BATCH * HD);
    }

    // =================== s1: h1 recurrence chain (waits gi1) ======================
    cudaStreamWaitEvent(s1, eGi1, 0);
    for (int t = 0; t < TT; t++) {
        h16_gemm_nt<__half><<<gemm_grid(BATCH, 3 * CD), 256, SMEM_P, s1>>>(
            h1h, whh1h, b_hh1, gh1, BATCH, 3 * CD, CD, 0, mt, t, 0);
        gru1_att_sorted<<<(BATCH * (CD / 2) + EW - 1) / EW, EW, 0, s1>>>(
            gi1a, gh1, caption, fvq, perm, mt, h1, h1h, atta, alphas, t);
        cudaEventRecord(evA[t], s1);
    }

    // =================== s2: h2 chain — ONE combined GEMM + cell per step =========
    cudaStreamWaitEvent(s2, eW2, 0);
    for (int t = 0; t < TT; t++) {
        cudaStreamWaitEvent(s2, evA[t], 0);
        h16_gemm_cat<<<gemm_grid(BATCH, N4), 256, SMEM_P, s2>>>(
            atta + (size_t)t * BATCH * CD, h2h, w2cat, b2cat, comb, mt, t);
        gru2_comb<<<(BATCH * (HD / 2) + EW - 1) / EW, EW, 0, s2>>>(
            comb, mt, h2, h2h, h2ah, t);
        cudaEventRecord(evC[t], s2);
    }

    // =================== main: per-step Wfc slabs (after gru2(t), wfch) ===========
    cudaStreamWaitEvent(0, eWf, 0);
    for (int t = 0; t < TT; t++) {
        cudaStreamWaitEvent(0, evC[t], 0);
        h16_gemm_nt<float><<<gemm_grid(BATCH, HD), 256, SMEM_P>>>(
            h2ah + (size_t)t * BATCH * HD, wfch, nullptr,
            y + (size_t)t * BATCH * HD,
            BATCH, HD, HD, 0, mt, t, 0);
    }

    maxreduce_out<<<(BATCH * HD + EW - 1) / EW, EW>>>(y, cap_len, rankof, out);
}

// round 15
// speedup vs baseline: 1.1357x; 1.1357x over previous
#include <cuda_runtime.h>
#include <cuda_fp16.h>
#include <cstdint>
#include <math.h>

// Problem dims (fixed)
#define BATCH 2048
#define TT    20
#define CD    512
#define HD    1024
#define VD    2048
#define QD    1024

// ---------------- fp32 scratch (rank-sorted / time-major layouts) -------------
__device__ float g_fv   [BATCH * CD];
__device__ float g_fq   [BATCH * CD];
__device__ float g_fvq  [BATCH * CD];
__device__ float g_h1   [BATCH * CD];
__device__ float g_h2   [BATCH * HD];
__device__ float g_y    [(size_t)TT * BATCH * HD];

// ---------------- fp16 scratch --------------------------------------------------
__device__ __half g_gi1a [(size_t)TT * BATCH * 3 * CD];  // time-major sorted
__device__ __half g_gh1  [BATCH * 3 * CD];
__device__ __half g_gi2a [(size_t)TT * BATCH * 3 * HD];  // time-major sorted
__device__ __half g_gh2  [BATCH * 3 * HD];
__device__ __half g_c16s [(size_t)TT * BATCH * CD];
__device__ __half g_v16s [BATCH * VD];
__device__ __half g_q16s [BATCH * QD];
__device__ __half g_wih1h[3 * CD * CD];
__device__ __half g_whh1h[3 * CD * CD];
__device__ __half g_wih2h[3 * HD * CD];
__device__ __half g_whh2h[3 * HD * HD];
__device__ __half g_wvh  [CD * VD];
__device__ __half g_wqh  [CD * QD];
__device__ __half g_wfch [HD * HD];
__device__ __half g_h1h  [BATCH * CD];
__device__ __half g_h2h  [BATCH * HD];
__device__ __half g_atta [(size_t)TT * BATCH * CD];
__device__ __half g_h2ah [(size_t)TT * BATCH * HD];

// ---------------- sorting metadata ----------------------------------------------
__device__ int g_perm [BATCH];
__device__ int g_rank [BATCH];
__device__ int g_mt   [TT];

// ---------------- helpers --------------------------------------------------------
__device__ __forceinline__ float sigmf(float x) { return 1.0f / (1.0f + expf(-x)); }
__device__ __forceinline__ float leakyf(float x) { return x > 0.0f ? x : 0.01f * x; }

__device__ __forceinline__ void mma_f16(
    float& c0, float& c1, float& c2, float& c3,
    uint32_t a0, uint32_t a1, uint32_t a2, uint32_t a3,
    uint32_t b0, uint32_t b1)
{
    asm volatile(
        "mma.sync.aligned.m16n8k16.row.col.f32.f16.f16.f32 "
        "{%0,%1,%2,%3}, {%4,%5,%6,%7}, {%8,%9}, {%0,%1,%2,%3};"
        : "+f"(c0), "+f"(c1), "+f"(c2), "+f"(c3)
        : "r"(a0), "r"(a1), "r"(a2), "r"(a3), "r"(b0), "r"(b1));
}

__device__ __forceinline__ void ldm_x4(uint32_t& r0, uint32_t& r1, uint32_t& r2, uint32_t& r3,
                                       uint32_t saddr)
{
    asm volatile("ldmatrix.sync.aligned.m8n8.x4.shared.b16 {%0,%1,%2,%3}, [%4];"
                 : "=r"(r0), "=r"(r1), "=r"(r2), "=r"(r3) : "r"(saddr));
}

__device__ __forceinline__ void cp16(uint32_t saddr, const void* gptr) {
    asm volatile("cp.async.cg.shared.global [%0], [%1], 16;" :: "r"(saddr), "l"(gptr));
}
__device__ __forceinline__ void cp_commit() { asm volatile("cp.async.commit_group;"); }
__device__ __forceinline__ void cp_wait3()  { asm volatile("cp.async.wait_group 3;"); }

__device__ __forceinline__ void store2(float* p, float v0, float v1) {
    *(float2*)p = make_float2(v0, v1);
}
__device__ __forceinline__ void store2(__half* p, float v0, float v1) {
    *(__half2*)p = __floats2half2_rn(v0, v1);
}

// ================= fp16 GEMM engine, 128x128 tile =================
#define LDSH 40
#define TILEB (128 * LDSH * 2)
#define STAGEB_P (2 * TILEB)
#define NSTG 5
#define SMEM_P (NSTG * STAGEB_P)     // 102400 bytes

template<typename OT>
__global__ __launch_bounds__(256, 2) void h16_gemm_nt(
    const __half* __restrict__ A, const __half* __restrict__ B,
    const float* __restrict__ bias, OT* __restrict__ C,
    int M, int N, int K, int epi,
    const int* __restrict__ mlim, int tsel, int tmaj)
{
    extern __shared__ __align__(16) char smem[];
    const int bm = blockIdx.y * 128;
    const int bn = blockIdx.x * 128;

    if (mlim) {
        if (tmaj) {
            if ((bm & 2047) >= mlim[bm >> 11]) return;
        } else {
            if (bm >= mlim[tsel]) return;
        }
    }

    const int tid  = threadIdx.x;
    const int wid  = tid >> 5;
    const int lane = tid & 31;
    const int wm   = wid >> 1;
    const int wn   = wid & 1;
    const int g    = lane >> 2;
    const int t    = lane & 3;

    const __half* Ag = A + (size_t)bm * K;
    const __half* Bg = B + (size_t)bn * K;
    const uint32_t sbase = (uint32_t)__cvta_generic_to_shared(smem);

    const int r0s = tid >> 2, v0s = tid & 3;
    const int r1s = (tid + 256) >> 2, v1s = tid & 3;

    const uint32_t a_off = (uint32_t)(((lane & 15) * LDSH + (lane >> 4) * 8) * 2);
    const int b_row = ((lane >> 4) << 3) + (lane & 7);
    const uint32_t b_koff = (uint32_t)((((lane >> 3) & 1) * 8) * 2);

    float acc[2][8][4];
#pragma unroll
    for (int i = 0; i < 2; i++)
#pragma unroll
        for (int j = 0; j < 8; j++)
#pragma unroll
            for (int r = 0; r < 4; r++) acc[i][j][r] = 0.0f;

    const int NKC = K >> 5;

    auto issue = [&](int kc) {
        const int st = kc % NSTG;
        const uint32_t sa = sbase + st * STAGEB_P;
        const uint32_t sb = sa + TILEB;
        const uint32_t o0 = (uint32_t)((r0s * LDSH + v0s * 8) * 2);
        const uint32_t o1 = (uint32_t)((r1s * LDSH + v1s * 8) * 2);
        cp16(sa + o0, Ag + (size_t)r0s * K + kc * 32 + v0s * 8);
        cp16(sb + o0, Bg + (size_t)r0s * K + kc * 32 + v0s * 8);
        cp16(sa + o1, Ag + (size_t)r1s * K + kc * 32 + v1s * 8);
        cp16(sb + o1, Bg + (size_t)r1s * K + kc * 32 + v1s * 8);
        cp_commit();
    };

    issue(0); issue(1); issue(2); issue(3);

    for (int kc = 0; kc < NKC; kc++) {
        cp_wait3();
        __syncthreads();
        const int st = kc % NSTG;
        const uint32_t cAb = sbase + st * STAGEB_P;
        const uint32_t cBb = cAb + TILEB;
#pragma unroll
        for (int ks = 0; ks < 2; ks++) {
            const uint32_t kso = (uint32_t)(ks * 16 * 2);
            uint32_t af[2][4];
#pragma unroll
            for (int mt = 0; mt < 2; mt++) {
                const uint32_t addr = cAb + (uint32_t)((wm * 32 + mt * 16) * LDSH * 2)
                                     + a_off + kso;
                ldm_x4(af[mt][0], af[mt][1], af[mt][2], af[mt][3], addr);
            }
            uint32_t bf[8][2];
#pragma unroll
            for (int p = 0; p < 4; p++) {
                const uint32_t addr = cBb
                    + (uint32_t)(((wn * 64 + p * 16 + b_row) * LDSH) * 2)
                    + kso + b_koff;
                ldm_x4(bf[2 * p][0], bf[2 * p][1], bf[2 * p + 1][0], bf[2 * p + 1][1], addr);
            }
#pragma unroll
            for (int mt = 0; mt < 2; mt++)
#pragma unroll
                for (int nt = 0; nt < 8; nt++)
                    mma_f16(acc[mt][nt][0], acc[mt][nt][1],
                            acc[mt][nt][2], acc[mt][nt][3],
                            af[mt][0], af[mt][1], af[mt][2], af[mt][3],
                            bf[nt][0], bf[nt][1]);
        }
        const int nxt = kc + 4;
        if (nxt < NKC) issue(nxt);
    }

#pragma unroll
    for (int mt = 0; mt < 2; mt++) {
        const int r0 = bm + wm * 32 + mt * 16 + g;
#pragma unroll
        for (int nt = 0; nt < 8; nt++) {
            const int col = bn + wn * 64 + nt * 8 + 2 * t;
            float b0 = 0.0f, b1 = 0.0f;
            if (bias) { b0 = bias[col]; b1 = bias[col + 1]; }
            float v0 = acc[mt][nt][0] + b0;
            float v1 = acc[mt][nt][1] + b1;
            float v2 = acc[mt][nt][2] + b0;
            float v3 = acc[mt][nt][3] + b1;
            if (epi == 1) { v0 = leakyf(v0); v1 = leakyf(v1); v2 = leakyf(v2); v3 = leakyf(v3); }
            store2(C + (size_t)r0 * N + col, v0, v1);
            store2(C + (size_t)(r0 + 8) * N + col, v2, v3);
        }
    }
}

// ---------------- sorting / permutation kernels ----------------------------------
__global__ void rank_kernel(const int* __restrict__ len,
                            int* __restrict__ perm, int* __restrict__ rankof)
{
    __shared__ int sl[BATCH];
    const int tid = threadIdx.x;
    for (int i = tid; i < BATCH; i += 1024) sl[i] = len[i];
    __syncthreads();
    for (int b = tid; b < BATCH; b += 1024) {
        const int lb = sl[b];
        int rk = 0;
        for (int b2 = 0; b2 < BATCH; b2++) {
            const int l2 = sl[b2];
            rk += (l2 > lb) || (l2 == lb && b2 < b);
        }
        perm[rk] = b;
        rankof[b] = rk;
    }
}

__global__ void mt_kernel(const int* __restrict__ len, int* __restrict__ mt) {
    const int t = threadIdx.x;
    if (t >= TT) return;
    int c = 0;
    for (int b = 0; b < BATCH; b++) c += (len[b] > t);
    mt[t] = c;
}

__global__ void f2h_kernel(const float* __restrict__ src, __half* __restrict__ dst, int n) {
    int i = (blockIdx.x * blockDim.x + threadIdx.x) * 4;
    if (i < n) {
        float4 f = *(const float4*)(src + i);
        *(__half2*)(dst + i)     = __floats2half2_rn(f.x, f.y);
        *(__half2*)(dst + i + 2) = __floats2half2_rn(f.z, f.w);
    }
}

__global__ void f2h_perm_kernel(const float* __restrict__ src, __half* __restrict__ dst,
                                const int* __restrict__ perm, int rowlen, int nrows)
{
    int idx = blockIdx.x * blockDim.x + threadIdx.x;
    const int vpr = rowlen / 4;
    if (idx >= nrows * vpr) return;
    const int r = idx / vpr, v = idx - r * vpr;
    const int b = perm[r];
    float4 f = *(const float4*)(src + (size_t)b * rowlen + v * 4);
    __half* d = dst + (size_t)r * rowlen + v * 4;
    *(__half2*)(d)     = __floats2half2_rn(f.x, f.y);
    *(__half2*)(d + 2) = __floats2half2_rn(f.z, f.w);
}

__global__ void permcap_kernel(const float* __restrict__ cap, __half* __restrict__ dst,
                               const int* __restrict__ perm)
{
    int idx = blockIdx.x * blockDim.x + threadIdx.x;
    const int vpr = CD / 4;
    if (idx >= TT * BATCH * vpr) return;
    const int v = idx % vpr;
    const int row = idx / vpr;
    const int r = row & (BATCH - 1);
    const int t = row >> 11;
    const int b = perm[r];
    float4 f = *(const float4*)(cap + ((size_t)b * TT + t) * CD + v * 4);
    __half* d = dst + (size_t)row * CD + v * 4;
    *(__half2*)(d)     = __floats2half2_rn(f.x, f.y);
    *(__half2*)(d + 2) = __floats2half2_rn(f.z, f.w);
}

__global__ void zero_state_kernel(float* __restrict__ f, __half* __restrict__ h, int n) {
    int i = blockIdx.x * blockDim.x + threadIdx.x;
    if (i < n) { f[i] = 0.0f; h[i] = __float2half(0.0f); }
}

__global__ void add_kernel(const float* __restrict__ a, const float* __restrict__ b,
                           float* __restrict__ c, int n) {
    int i = blockIdx.x * blockDim.x + threadIdx.x;
    if (i < n) c[i] = a[i] + b[i];
}

// ---------------- packed GRU elementwise kernels -----------------------------------
__global__ void gru1_att_sorted(
    const __half* __restrict__ gi1a,
    const __half* __restrict__ gh1,
    const float* __restrict__ caption,
    const float* __restrict__ fvqs,
    const int*   __restrict__ perm,
    const int*   __restrict__ mt,
    float* __restrict__ h1, __half* __restrict__ h1h,
    __half* __restrict__ atta,
    float* __restrict__ alphas,
    int t)
{
    int idx = blockIdx.x * blockDim.x + threadIdx.x;
    if (idx >= BATCH * (CD / 2)) return;
    const int r = idx / (CD / 2);
    const int j = (idx - r * (CD / 2)) * 2;
    const int b = perm[r];
    float* alp = alphas + ((size_t)b * TT + t) * CD + j;

    if (r >= mt[t]) {
        *(float2*)alp = make_float2(0.0f, 0.0f);
        return;
    }

    const __half* gi = gi1a + ((size_t)t * BATCH + r) * (3 * CD);
    const __half* gh = gh1 + (size_t)r * (3 * CD);

    float2 hv = *(float2*)(h1 + (size_t)r * CD + j);
    float2 gir = __half22float2(*(const __half2*)(gi + j));
    float2 giz = __half22float2(*(const __half2*)(gi + CD + j));
    float2 gin = __half22float2(*(const __half2*)(gi + 2 * CD + j));
    float2 ghr = __half22float2(*(const __half2*)(gh + j));
    float2 ghz = __half22float2(*(const __half2*)(gh + CD + j));
    float2 ghn = __half22float2(*(const __half2*)(gh + 2 * CD + j));

    float r0 = sigmf(gir.x + ghr.x), r1 = sigmf(gir.y + ghr.y);
    float z0 = sigmf(giz.x + ghz.x), z1 = sigmf(giz.y + ghz.y);
    float n0 = tanhf(gin.x + r0 * ghn.x), n1 = tanhf(gin.y + r1 * ghn.y);
    float h0 = (1.0f - z0) * n0 + z0 * hv.x;
    float h1v = (1.0f - z1) * n1 + z1 * hv.y;

    *(float2*)(h1 + (size_t)r * CD + j) = make_float2(h0, h1v);
    *(__half2*)(h1h + (size_t)r * CD + j) = __floats2half2_rn(h0, h1v);

    float2 x = *(const float2*)(caption + ((size_t)b * TT + t) * CD + j);
    float2 fq = *(const float2*)(fvqs + (size_t)r * CD + j);
    float a0 = sigmf(h0 * fq.x) * x.x;
    float a1 = sigmf(h1v * fq.y) * x.y;
    *(__half2*)(atta + ((size_t)t * BATCH + r) * CD + j) = __floats2half2_rn(a0, a1);
    *(float2*)alp = make_float2(a0, a1);
}

__global__ void gru2_sorted(
    const __half* __restrict__ gi2a,
    const __half* __restrict__ gh2,
    const int*   __restrict__ mt,
    float* __restrict__ h2, __half* __restrict__ h2h,
    __half* __restrict__ h2ah,
    int t)
{
    int idx = blockIdx.x * blockDim.x + threadIdx.x;
    if (idx >= BATCH * (HD / 2)) return;
    const int r = idx / (HD / 2);
    const int j = (idx - r * (HD / 2)) * 2;
    if (r >= mt[t]) return;

    const __half* gi = gi2a + ((size_t)t * BATCH + r) * (3 * HD);
    const __half* gh = gh2 + (size_t)r * (3 * HD);

    float2 hv = *(float2*)(h2 + (size_t)r * HD + j);
    float2 gir = __half22float2(*(const __half2*)(gi + j));
    float2 giz = __half22float2(*(const __half2*)(gi + HD + j));
    float2 gin = __half22float2(*(const __half2*)(gi + 2 * HD + j));
    float2 ghr = __half22float2(*(const __half2*)(gh + j));
    float2 ghz = __half22float2(*(const __half2*)(gh + HD + j));
    float2 ghn = __half22float2(*(const __half2*)(gh + 2 * HD + j));

    float r0 = sigmf(gir.x + ghr.x), r1 = sigmf(gir.y + ghr.y);
    float z0 = sigmf(giz.x + ghz.x), z1 = sigmf(giz.y + ghz.y);
    float n0 = tanhf(gin.x + r0 * ghn.x), n1 = tanhf(gin.y + r1 * ghn.y);
    float h0 = (1.0f - z0) * n0 + z0 * hv.x;
    float h1v = (1.0f - z1) * n1 + z1 * hv.y;

    *(float2*)(h2 + (size_t)r * HD + j) = make_float2(h0, h1v);
    __half2 hh = __floats2half2_rn(h0, h1v);
    *(__half2*)(h2h + (size_t)r * HD + j) = hh;
    *(__half2*)(h2ah + ((size_t)t * BATCH + r) * HD + j) = hh;
}

__global__ void maxreduce_out(
    const float* __restrict__ y,
    const int*   __restrict__ cap_len,
    const int*   __restrict__ rankof,
    float* __restrict__ out)
{
    int idx = blockIdx.x * blockDim.x + threadIdx.x;
    if (idx >= BATCH * HD) return;
    const int b = idx / HD, j = idx - b * HD;
    const int len = cap_len[b];
    const int r = rankof[b];
    float m = 0.0f;
    for (int t = 0; t < len; t++)
        m = fmaxf(m, leakyf(y[((size_t)t * BATCH + r) * HD + j]));
    out[idx] = m;
}

// ---------------- launch ------------------------------------------------------------
static inline dim3 gemm_grid(int M, int N) { return dim3(N / 128, M / 128); }

extern "C" void kernel_launch(void* const* d_in, const int* in_sizes, int n_in,
                              void* d_out, int out_size)
{
    const float* v       = (const float*)d_in[0];
    const float* q       = (const float*)d_in[1];
    const float* caption = (const float*)d_in[2];
    const int*   cap_len = (const int*)  d_in[3];
    const float* w_ih1   = (const float*)d_in[4];
    const float* w_hh1   = (const float*)d_in[5];
    const float* b_ih1   = (const float*)d_in[6];
    const float* b_hh1   = (const float*)d_in[7];
    const float* w_ih2   = (const float*)d_in[8];
    const float* w_hh2   = (const float*)d_in[9];
    const float* b_ih2   = (const float*)d_in[10];
    const float* b_hh2   = (const float*)d_in[11];
    const float* Wv      = (const float*)d_in[12];
    const float* Wq      = (const float*)d_in[13];
    const float* Wfc     = (const float*)d_in[14];

    float* out    = (float*)d_out;
    float* alphas = (float*)d_out + (size_t)BATCH * HD;

    float *fv, *fq, *fvq, *h1, *h2, *y;
    cudaGetSymbolAddress((void**)&fv,   g_fv);
    cudaGetSymbolAddress((void**)&fq,   g_fq);
    cudaGetSymbolAddress((void**)&fvq,  g_fvq);
    cudaGetSymbolAddress((void**)&h1,   g_h1);
    cudaGetSymbolAddress((void**)&h2,   g_h2);
    cudaGetSymbolAddress((void**)&y,    g_y);

    __half *gi1a, *gh1, *gi2a, *gh2;
    __half *c16s, *v16s, *q16s, *wih1h, *whh1h, *wih2h, *whh2h, *wvh, *wqh, *wfch;
    __half *h1h, *h2h, *atta, *h2ah;
    cudaGetSymbolAddress((void**)&gi1a,  g_gi1a);
    cudaGetSymbolAddress((void**)&gh1,   g_gh1);
    cudaGetSymbolAddress((void**)&gi2a,  g_gi2a);
    cudaGetSymbolAddress((void**)&gh2,   g_gh2);
    cudaGetSymbolAddress((void**)&c16s,  g_c16s);
    cudaGetSymbolAddress((void**)&v16s,  g_v16s);
    cudaGetSymbolAddress((void**)&q16s,  g_q16s);
    cudaGetSymbolAddress((void**)&wih1h, g_wih1h);
    cudaGetSymbolAddress((void**)&whh1h, g_whh1h);
    cudaGetSymbolAddress((void**)&wih2h, g_wih2h);
    cudaGetSymbolAddress((void**)&whh2h, g_whh2h);
    cudaGetSymbolAddress((void**)&wvh,   g_wvh);
    cudaGetSymbolAddress((void**)&wqh,   g_wqh);
    cudaGetSymbolAddress((void**)&wfch,  g_wfch);
    cudaGetSymbolAddress((void**)&h1h,   g_h1h);
    cudaGetSymbolAddress((void**)&h2h,   g_h2h);
    cudaGetSymbolAddress((void**)&atta,  g_atta);
    cudaGetSymbolAddress((void**)&h2ah,  g_h2ah);

    int *perm, *rankof, *mt;
    cudaGetSymbolAddress((void**)&perm,   g_perm);
    cudaGetSymbolAddress((void**)&rankof, g_rank);
    cudaGetSymbolAddress((void**)&mt,     g_mt);

    cudaFuncSetAttribute(h16_gemm_nt<float>,
                         cudaFuncAttributeMaxDynamicSharedMemorySize, SMEM_P);
    cudaFuncSetAttribute(h16_gemm_nt<__half>,
                         cudaFuncAttributeMaxDynamicSharedMemorySize, SMEM_P);

    // ---- one-time stream/event creation ----
    static cudaStream_t s1 = nullptr, s2 = nullptr, s3 = nullptr;
    static cudaEvent_t ePre, eCap, eFq, eW2, eY;
    static cudaEvent_t evG[TT], evA[TT], evB[TT], evC[TT];
    if (!s1) {
        int loPri, hiPri;
        cudaDeviceGetStreamPriorityRange(&loPri, &hiPri);
        cudaStreamCreateWithPriority(&s1, cudaStreamNonBlocking, hiPri);
        cudaStreamCreateWithPriority(&s2, cudaStreamNonBlocking, hiPri);
        cudaStreamCreateWithPriority(&s3, cudaStreamNonBlocking, loPri);
        cudaEventCreateWithFlags(&ePre, cudaEventDisableTiming);
        cudaEventCreateWithFlags(&eCap, cudaEventDisableTiming);
        cudaEventCreateWithFlags(&eFq,  cudaEventDisableTiming);
        cudaEventCreateWithFlags(&eW2,  cudaEventDisableTiming);
        cudaEventCreateWithFlags(&eY,   cudaEventDisableTiming);
        for (int i = 0; i < TT; i++) {
            cudaEventCreateWithFlags(&evG[i], cudaEventDisableTiming);
            cudaEventCreateWithFlags(&evA[i], cudaEventDisableTiming);
            cudaEventCreateWithFlags(&evB[i], cudaEventDisableTiming);
            cudaEventCreateWithFlags(&evC[i], cudaEventDisableTiming);
        }
    }

    const int EW = 256;

    // =================== shared prefix on main: sort metadata =====================
    rank_kernel<<<1, 1024>>>(cap_len, perm, rankof);
    mt_kernel<<<1, 32>>>(cap_len, mt);
    cudaEventRecord(ePre, 0);
    cudaStreamWaitEvent(s1, ePre, 0);
    cudaStreamWaitEvent(s2, ePre, 0);

    // =================== main: caption fp16 + wih1 cvt ============================
    f2h_kernel<<<(3 * CD * CD / 4 + EW - 1) / EW, EW>>>(w_ih1, wih1h, 3 * CD * CD);
    permcap_kernel<<<(TT * BATCH * (CD / 4) + EW - 1) / EW, EW>>>(caption, c16s, perm);
    cudaEventRecord(eCap, 0);
    cudaStreamWaitEvent(s3, eCap, 0);

    // =================== s3: per-step gi1 slabs (A offset t*B*CD) =================
    for (int t = 0; t < TT; t++) {
        h16_gemm_nt<__half><<<gemm_grid(BATCH, 3 * CD), 256, SMEM_P, s3>>>(
            c16s + (size_t)t * BATCH * CD, wih1h, b_ih1,
            gi1a + (size_t)t * BATCH * 3 * CD,
            BATCH, 3 * CD, CD, 0, mt, t, 0);
        cudaEventRecord(evG[t], s3);
    }
    // s3 then converts Wfc (needed later for Wfc slabs on s3)
    f2h_kernel<<<(HD * HD / 4 + EW - 1) / EW, EW, 0, s3>>>(Wfc, wfch, HD * HD);

    // =================== s2: fq GEMM + GRU2 weight cvts + h2 init =================
    f2h_kernel<<<(CD * QD / 4 + EW - 1) / EW, EW, 0, s2>>>(Wq, wqh, CD * QD);
    f2h_perm_kernel<<<(BATCH * (QD / 4) + EW - 1) / EW, EW, 0, s2>>>(q, q16s, perm, QD, BATCH);
    h16_gemm_nt<float><<<gemm_grid(BATCH, CD), 256, SMEM_P, s2>>>(
        q16s, wqh, nullptr, fq, BATCH, CD, QD, 1, nullptr, 0, 0);
    cudaEventRecord(eFq, s2);
    f2h_kernel<<<(3 * HD * CD / 4 + EW - 1) / EW, EW, 0, s2>>>(w_ih2, wih2h, 3 * HD * CD);
    cudaEventRecord(eW2, s2);
    f2h_kernel<<<(3 * HD * HD / 4 + EW - 1) / EW, EW, 0, s2>>>(w_hh2, whh2h, 3 * HD * HD);
    zero_state_kernel<<<(BATCH * HD + EW - 1) / EW, EW, 0, s2>>>(h2, h2h, BATCH * HD);

    // =================== s1: fv GEMM + fvq + h1 init + whh1 cvt ===================
    f2h_kernel<<<(3 * CD * CD / 4 + EW - 1) / EW, EW, 0, s1>>>(w_hh1, whh1h, 3 * CD * CD);
    f2h_kernel<<<(CD * VD / 4 + EW - 1) / EW, EW, 0, s1>>>(Wv, wvh, CD * VD);
    f2h_perm_kernel<<<(BATCH * (VD / 4) + EW - 1) / EW, EW, 0, s1>>>(v, v16s, perm, VD, BATCH);
    h16_gemm_nt<float><<<gemm_grid(BATCH, CD), 256, SMEM_P, s1>>>(
        v16s, wvh, nullptr, fv, BATCH, CD, VD, 1, nullptr, 0, 0);
    cudaStreamWaitEvent(s1, eFq, 0);
    add_kernel<<<(BATCH * CD + EW - 1) / EW, EW, 0, s1>>>(fv, fq, fvq, BATCH * CD);
    zero_state_kernel<<<(BATCH * CD + EW - 1) / EW, EW, 0, s1>>>(h1, h1h, BATCH * CD);

    // =================== s1: h1 recurrence chain (waits gi1 slab t) ===============
    for (int t = 0; t < TT; t++) {
        cudaStreamWaitEvent(s1, evG[t], 0);
        h16_gemm_nt<__half><<<gemm_grid(BATCH, 3 * CD), 256, SMEM_P, s1>>>(
            h1h, whh1h, b_hh1, gh1, BATCH, 3 * CD, CD, 0, mt, t, 0);
        gru1_att_sorted<<<(BATCH * (CD / 2) + EW - 1) / EW, EW, 0, s1>>>(
            gi1a, gh1, caption, fvq, perm, mt, h1, h1h, atta, alphas, t);
        cudaEventRecord(evA[t], s1);
    }

    // =================== main: per-step gi2 slabs (after gru1(t), wih2h) ==========
    cudaStreamWaitEvent(0, eW2, 0);
    for (int t = 0; t < TT; t++) {
        cudaStreamWaitEvent(0, evA[t], 0);
        h16_gemm_nt<__half><<<gemm_grid(BATCH, 3 * HD), 256, SMEM_P>>>(
            atta + (size_t)t * BATCH * CD, wih2h, b_ih2,
            gi2a + (size_t)t * BATCH * 3 * HD,
            BATCH, 3 * HD, CD, 0, mt, t, 0);
        cudaEventRecord(evB[t], 0);
    }

    // =================== s2: h2 recurrence chain (after gi2 slab(t)) ==============
    for (int t = 0; t < TT; t++) {
        cudaStreamWaitEvent(s2, evB[t], 0);
        h16_gemm_nt<__half><<<gemm_grid(BATCH, 3 * HD), 256, SMEM_P, s2>>>(
            h2h, whh2h, b_hh2, gh2, BATCH, 3 * HD, HD, 0, mt, t, 0);
        gru2_sorted<<<(BATCH * (HD / 2) + EW - 1) / EW, EW, 0, s2>>>(
            gi2a, gh2, mt, h2, h2h, h2ah, t);
        cudaEventRecord(evC[t], s2);
    }

    // =================== s3: per-step Wfc slabs (after gru2(t)) ===================
    for (int t = 0; t < TT; t++) {
        cudaStreamWaitEvent(s3, evC[t], 0);
        h16_gemm_nt<float><<<gemm_grid(BATCH, HD), 256, SMEM_P, s3>>>(
            h2ah + (size_t)t * BATCH * HD, wfch, nullptr,
            y + (size_t)t * BATCH * HD,
            BATCH, HD, HD, 0, mt, t, 0);
    }
    cudaEventRecord(eY, s3);

    // =================== main: join + final reduction =============================
    cudaStreamWaitEvent(0, eY, 0);
    maxreduce_out<<<(BATCH * HD + EW - 1) / EW, EW>>>(y, cap_len, rankof, out);
}

// round 16
// speedup vs baseline: 1.1398x; 1.0036x over previous
#include <cuda_runtime.h>
#include <cuda_fp16.h>
#include <cstdint>
#include <math.h>

// Problem dims (fixed)
#define BATCH 2048
#define TT    20
#define CD    512
#define HD    1024
#define VD    2048
#define QD    1024

// ---------------- fp32 scratch (rank-sorted / time-major layouts) -------------
__device__ float g_fv   [BATCH * CD];
__device__ float g_fq   [BATCH * CD];
__device__ float g_fvq  [BATCH * CD];
__device__ float g_h1   [BATCH * CD];
__device__ float g_h2   [BATCH * HD];
__device__ float g_y    [(size_t)TT * BATCH * HD];

// ---------------- fp16 scratch --------------------------------------------------
__device__ __half g_gi1a [(size_t)TT * BATCH * 3 * CD];  // time-major sorted
__device__ __half g_gh1  [BATCH * 3 * CD];
__device__ __half g_gi2a [(size_t)TT * BATCH * 3 * HD];  // time-major sorted
__device__ __half g_gh2  [BATCH * 3 * HD];
__device__ __half g_c16s [(size_t)TT * BATCH * CD];
__device__ __half g_v16s [BATCH * VD];
__device__ __half g_q16s [BATCH * QD];
__device__ __half g_wih1h[3 * CD * CD];
__device__ __half g_whh1h[3 * CD * CD];
__device__ __half g_wih2h[3 * HD * CD];
__device__ __half g_whh2h[3 * HD * HD];
__device__ __half g_wvh  [CD * VD];
__device__ __half g_wqh  [CD * QD];
__device__ __half g_wfch [HD * HD];
__device__ __half g_h1h  [BATCH * CD];
__device__ __half g_h2h  [BATCH * HD];
__device__ __half g_atta [(size_t)TT * BATCH * CD];
__device__ __half g_h2ah [(size_t)TT * BATCH * HD];

// ---------------- sorting metadata ----------------------------------------------
__device__ int g_perm [BATCH];
__device__ int g_rank [BATCH];
__device__ int g_mt   [TT];

// ---------------- helpers --------------------------------------------------------
__device__ __forceinline__ float sigmf(float x) { return 1.0f / (1.0f + expf(-x)); }
__device__ __forceinline__ float leakyf(float x) { return x > 0.0f ? x : 0.01f * x; }

__device__ __forceinline__ void mma_f16(
    float& c0, float& c1, float& c2, float& c3,
    uint32_t a0, uint32_t a1, uint32_t a2, uint32_t a3,
    uint32_t b0, uint32_t b1)
{
    asm volatile(
        "mma.sync.aligned.m16n8k16.row.col.f32.f16.f16.f32 "
        "{%0,%1,%2,%3}, {%4,%5,%6,%7}, {%8,%9}, {%0,%1,%2,%3};"
        : "+f"(c0), "+f"(c1), "+f"(c2), "+f"(c3)
        : "r"(a0), "r"(a1), "r"(a2), "r"(a3), "r"(b0), "r"(b1));
}

__device__ __forceinline__ void ldm_x4(uint32_t& r0, uint32_t& r1, uint32_t& r2, uint32_t& r3,
                                       uint32_t saddr)
{
    asm volatile("ldmatrix.sync.aligned.m8n8.x4.shared.b16 {%0,%1,%2,%3}, [%4];"
                 : "=r"(r0), "=r"(r1), "=r"(r2), "=r"(r3) : "r"(saddr));
}

__device__ __forceinline__ void cp16(uint32_t saddr, const void* gptr) {
    asm volatile("cp.async.cg.shared.global [%0], [%1], 16;" :: "r"(saddr), "l"(gptr));
}
__device__ __forceinline__ void cp_commit() { asm volatile("cp.async.commit_group;"); }
__device__ __forceinline__ void cp_wait3()  { asm volatile("cp.async.wait_group 3;"); }

__device__ __forceinline__ void store2(float* p, float v0, float v1) {
    *(float2*)p = make_float2(v0, v1);
}
__device__ __forceinline__ void store2(__half* p, float v0, float v1) {
    *(__half2*)p = __floats2half2_rn(v0, v1);
}

// ================= fp16 GEMM engine, 128x128 tile =================
#define LDSH 40
#define TILEB (128 * LDSH * 2)
#define STAGEB_P (2 * TILEB)
#define NSTG 5
#define SMEM_P (NSTG * STAGEB_P)     // 102400 bytes

template<typename OT>
__global__ __launch_bounds__(256, 2) void h16_gemm_nt(
    const __half* __restrict__ A, const __half* __restrict__ B,
    const float* __restrict__ bias, OT* __restrict__ C,
    int M, int N, int K, int epi,
    const int* __restrict__ mlim, int tsel, int tmaj)
{
    extern __shared__ __align__(16) char smem[];
    const int bm = blockIdx.y * 128;
    const int bn = blockIdx.x * 128;

    if (mlim) {
        if (tmaj) {
            if ((bm & 2047) >= mlim[bm >> 11]) return;
        } else {
            if (bm >= mlim[tsel]) return;
        }
    }

    const int tid  = threadIdx.x;
    const int wid  = tid >> 5;
    const int lane = tid & 31;
    const int wm   = wid >> 1;
    const int wn   = wid & 1;
    const int g    = lane >> 2;
    const int t    = lane & 3;

    const __half* Ag = A + (size_t)bm * K;
    const __half* Bg = B + (size_t)bn * K;
    const uint32_t sbase = (uint32_t)__cvta_generic_to_shared(smem);

    const int r0s = tid >> 2, v0s = tid & 3;
    const int r1s = (tid + 256) >> 2, v1s = tid & 3;

    const uint32_t a_off = (uint32_t)(((lane & 15) * LDSH + (lane >> 4) * 8) * 2);
    const int b_row = ((lane >> 4) << 3) + (lane & 7);
    const uint32_t b_koff = (uint32_t)((((lane >> 3) & 1) * 8) * 2);

    float acc[2][8][4];
#pragma unroll
    for (int i = 0; i < 2; i++)
#pragma unroll
        for (int j = 0; j < 8; j++)
#pragma unroll
            for (int r = 0; r < 4; r++) acc[i][j][r] = 0.0f;

    const int NKC = K >> 5;

    auto issue = [&](int kc) {
        const int st = kc % NSTG;
        const uint32_t sa = sbase + st * STAGEB_P;
        const uint32_t sb = sa + TILEB;
        const uint32_t o0 = (uint32_t)((r0s * LDSH + v0s * 8) * 2);
        const uint32_t o1 = (uint32_t)((r1s * LDSH + v1s * 8) * 2);
        cp16(sa + o0, Ag + (size_t)r0s * K + kc * 32 + v0s * 8);
        cp16(sb + o0, Bg + (size_t)r0s * K + kc * 32 + v0s * 8);
        cp16(sa + o1, Ag + (size_t)r1s * K + kc * 32 + v1s * 8);
        cp16(sb + o1, Bg + (size_t)r1s * K + kc * 32 + v1s * 8);
        cp_commit();
    };

    issue(0); issue(1); issue(2); issue(3);

    for (int kc = 0; kc < NKC; kc++) {
        cp_wait3();
        __syncthreads();
        const int st = kc % NSTG;
        const uint32_t cAb = sbase + st * STAGEB_P;
        const uint32_t cBb = cAb + TILEB;
#pragma unroll
        for (int ks = 0; ks < 2; ks++) {
            const uint32_t kso = (uint32_t)(ks * 16 * 2);
            uint32_t af[2][4];
#pragma unroll
            for (int mt = 0; mt < 2; mt++) {
                const uint32_t addr = cAb + (uint32_t)((wm * 32 + mt * 16) * LDSH * 2)
                                     + a_off + kso;
                ldm_x4(af[mt][0], af[mt][1], af[mt][2], af[mt][3], addr);
            }
            uint32_t bf[8][2];
#pragma unroll
            for (int p = 0; p < 4; p++) {
                const uint32_t addr = cBb
                    + (uint32_t)(((wn * 64 + p * 16 + b_row) * LDSH) * 2)
                    + kso + b_koff;
                ldm_x4(bf[2 * p][0], bf[2 * p][1], bf[2 * p + 1][0], bf[2 * p + 1][1], addr);
            }
#pragma unroll
            for (int mt = 0; mt < 2; mt++)
#pragma unroll
                for (int nt = 0; nt < 8; nt++)
                    mma_f16(acc[mt][nt][0], acc[mt][nt][1],
                            acc[mt][nt][2], acc[mt][nt][3],
                            af[mt][0], af[mt][1], af[mt][2], af[mt][3],
                            bf[nt][0], bf[nt][1]);
        }
        const int nxt = kc + 4;
        if (nxt < NKC) issue(nxt);
    }

#pragma unroll
    for (int mt = 0; mt < 2; mt++) {
        const int r0 = bm + wm * 32 + mt * 16 + g;
#pragma unroll
        for (int nt = 0; nt < 8; nt++) {
            const int col = bn + wn * 64 + nt * 8 + 2 * t;
            float b0 = 0.0f, b1 = 0.0f;
            if (bias) { b0 = bias[col]; b1 = bias[col + 1]; }
            float v0 = acc[mt][nt][0] + b0;
            float v1 = acc[mt][nt][1] + b1;
            float v2 = acc[mt][nt][2] + b0;
            float v3 = acc[mt][nt][3] + b1;
            if (epi == 1) { v0 = leakyf(v0); v1 = leakyf(v1); v2 = leakyf(v2); v3 = leakyf(v3); }
            store2(C + (size_t)r0 * N + col, v0, v1);
            store2(C + (size_t)(r0 + 8) * N + col, v2, v3);
        }
    }
}

// ---------------- sorting / permutation kernels ----------------------------------
__global__ void rank_kernel(const int* __restrict__ len,
                            int* __restrict__ perm, int* __restrict__ rankof)
{
    __shared__ int sl[BATCH];
    const int tid = threadIdx.x;
    for (int i = tid; i < BATCH; i += 1024) sl[i] = len[i];
    __syncthreads();
    for (int b = tid; b < BATCH; b += 1024) {
        const int lb = sl[b];
        int rk = 0;
        for (int b2 = 0; b2 < BATCH; b2++) {
            const int l2 = sl[b2];
            rk += (l2 > lb) || (l2 == lb && b2 < b);
        }
        perm[rk] = b;
        rankof[b] = rk;
    }
}

__global__ void mt_kernel(const int* __restrict__ len, int* __restrict__ mt) {
    const int t = threadIdx.x;
    if (t >= TT) return;
    int c = 0;
    for (int b = 0; b < BATCH; b++) c += (len[b] > t);
    mt[t] = c;
}

__global__ void f2h_kernel(const float* __restrict__ src, __half* __restrict__ dst, int n) {
    int i = (blockIdx.x * blockDim.x + threadIdx.x) * 4;
    if (i < n) {
        float4 f = *(const float4*)(src + i);
        *(__half2*)(dst + i)     = __floats2half2_rn(f.x, f.y);
        *(__half2*)(dst + i + 2) = __floats2half2_rn(f.z, f.w);
    }
}

__global__ void f2h_perm_kernel(const float* __restrict__ src, __half* __restrict__ dst,
                                const int* __restrict__ perm, int rowlen, int nrows)
{
    int idx = blockIdx.x * blockDim.x + threadIdx.x;
    const int vpr = rowlen / 4;
    if (idx >= nrows * vpr) return;
    const int r = idx / vpr, v = idx - r * vpr;
    const int b = perm[r];
    float4 f = *(const float4*)(src + (size_t)b * rowlen + v * 4);
    __half* d = dst + (size_t)r * rowlen + v * 4;
    *(__half2*)(d)     = __floats2half2_rn(f.x, f.y);
    *(__half2*)(d + 2) = __floats2half2_rn(f.z, f.w);
}

__global__ void permcap_kernel(const float* __restrict__ cap, __half* __restrict__ dst,
                               const int* __restrict__ perm)
{
    int idx = blockIdx.x * blockDim.x + threadIdx.x;
    const int vpr = CD / 4;
    if (idx >= TT * BATCH * vpr) return;
    const int v = idx % vpr;
    const int row = idx / vpr;
    const int r = row & (BATCH - 1);
    const int t = row >> 11;
    const int b = perm[r];
    float4 f = *(const float4*)(cap + ((size_t)b * TT + t) * CD + v * 4);
    __half* d = dst + (size_t)row * CD + v * 4;
    *(__half2*)(d)     = __floats2half2_rn(f.x, f.y);
    *(__half2*)(d + 2) = __floats2half2_rn(f.z, f.w);
}

__global__ void zero_state_kernel(float* __restrict__ f, __half* __restrict__ h, int n) {
    int i = blockIdx.x * blockDim.x + threadIdx.x;
    if (i < n) { f[i] = 0.0f; h[i] = __float2half(0.0f); }
}

__global__ void add_kernel(const float* __restrict__ a, const float* __restrict__ b,
                           float* __restrict__ c, int n) {
    int i = blockIdx.x * blockDim.x + threadIdx.x;
    if (i < n) c[i] = a[i] + b[i];
}

// ---------------- packed GRU elementwise kernels -----------------------------------
__global__ void gru1_att_sorted(
    const __half* __restrict__ gi1a,
    const __half* __restrict__ gh1,
    const float* __restrict__ caption,
    const float* __restrict__ fvqs,
    const int*   __restrict__ perm,
    const int*   __restrict__ mt,
    float* __restrict__ h1, __half* __restrict__ h1h,
    __half* __restrict__ atta,
    float* __restrict__ alphas,
    int t)
{
    int idx = blockIdx.x * blockDim.x + threadIdx.x;
    if (idx >= BATCH * (CD / 2)) return;
    const int r = idx / (CD / 2);
    const int j = (idx - r * (CD / 2)) * 2;
    const int b = perm[r];
    float* alp = alphas + ((size_t)b * TT + t) * CD + j;

    if (r >= mt[t]) {
        *(float2*)alp = make_float2(0.0f, 0.0f);
        return;
    }

    const __half* gi = gi1a + ((size_t)t * BATCH + r) * (3 * CD);
    const __half* gh = gh1 + (size_t)r * (3 * CD);

    float2 hv = *(float2*)(h1 + (size_t)r * CD + j);
    float2 gir = __half22float2(*(const __half2*)(gi + j));
    float2 giz = __half22float2(*(const __half2*)(gi + CD + j));
    float2 gin = __half22float2(*(const __half2*)(gi + 2 * CD + j));
    float2 ghr = __half22float2(*(const __half2*)(gh + j));
    float2 ghz = __half22float2(*(const __half2*)(gh + CD + j));
    float2 ghn = __half22float2(*(const __half2*)(gh + 2 * CD + j));

    float r0 = sigmf(gir.x + ghr.x), r1 = sigmf(gir.y + ghr.y);
    float z0 = sigmf(giz.x + ghz.x), z1 = sigmf(giz.y + ghz.y);
    float n0 = tanhf(gin.x + r0 * ghn.x), n1 = tanhf(gin.y + r1 * ghn.y);
    float h0 = (1.0f - z0) * n0 + z0 * hv.x;
    float h1v = (1.0f - z1) * n1 + z1 * hv.y;

    *(float2*)(h1 + (size_t)r * CD + j) = make_float2(h0, h1v);
    *(__half2*)(h1h + (size_t)r * CD + j) = __floats2half2_rn(h0, h1v);

    float2 x = *(const float2*)(caption + ((size_t)b * TT + t) * CD + j);
    float2 fq = *(const float2*)(fvqs + (size_t)r * CD + j);
    float a0 = sigmf(h0 * fq.x) * x.x;
    float a1 = sigmf(h1v * fq.y) * x.y;
    *(__half2*)(atta + ((size_t)t * BATCH + r) * CD + j) = __floats2half2_rn(a0, a1);
    *(float2*)alp = make_float2(a0, a1);
}

__global__ void gru2_sorted(
    const __half* __restrict__ gi2a,
    const __half* __restrict__ gh2,
    const int*   __restrict__ mt,
    float* __restrict__ h2, __half* __restrict__ h2h,
    __half* __restrict__ h2ah,
    int t)
{
    int idx = blockIdx.x * blockDim.x + threadIdx.x;
    if (idx >= BATCH * (HD / 2)) return;
    const int r = idx / (HD / 2);
    const int j = (idx - r * (HD / 2)) * 2;
    if (r >= mt[t]) return;

    const __half* gi = gi2a + ((size_t)t * BATCH + r) * (3 * HD);
    const __half* gh = gh2 + (size_t)r * (3 * HD);

    float2 hv = *(float2*)(h2 + (size_t)r * HD + j);
    float2 gir = __half22float2(*(const __half2*)(gi + j));
    float2 giz = __half22float2(*(const __half2*)(gi + HD + j));
    float2 gin = __half22float2(*(const __half2*)(gi + 2 * HD + j));
    float2 ghr = __half22float2(*(const __half2*)(gh + j));
    float2 ghz = __half22float2(*(const __half2*)(gh + HD + j));
    float2 ghn = __half22float2(*(const __half2*)(gh + 2 * HD + j));

    float r0 = sigmf(gir.x + ghr.x), r1 = sigmf(gir.y + ghr.y);
    float z0 = sigmf(giz.x + ghz.x), z1 = sigmf(giz.y + ghz.y);
    float n0 = tanhf(gin.x + r0 * ghn.x), n1 = tanhf(gin.y + r1 * ghn.y);
    float h0 = (1.0f - z0) * n0 + z0 * hv.x;
    float h1v = (1.0f - z1) * n1 + z1 * hv.y;

    *(float2*)(h2 + (size_t)r * HD + j) = make_float2(h0, h1v);
    __half2 hh = __floats2half2_rn(h0, h1v);
    *(__half2*)(h2h + (size_t)r * HD + j) = hh;
    *(__half2*)(h2ah + ((size_t)t * BATCH + r) * HD + j) = hh;
}

__global__ void maxreduce_out(
    const float* __restrict__ y,
    const int*   __restrict__ cap_len,
    const int*   __restrict__ rankof,
    float* __restrict__ out)
{
    int idx = blockIdx.x * blockDim.x + threadIdx.x;
    if (idx >= BATCH * HD) return;
    const int b = idx / HD, j = idx - b * HD;
    const int len = cap_len[b];
    const int r = rankof[b];
    float m = 0.0f;
    for (int t = 0; t < len; t++)
        m = fmaxf(m, leakyf(y[((size_t)t * BATCH + r) * HD + j]));
    out[idx] = m;
}

// ---------------- launch ------------------------------------------------------------
static inline dim3 gemm_grid(int M, int N) { return dim3(N / 128, M / 128); }

extern "C" void kernel_launch(void* const* d_in, const int* in_sizes, int n_in,
                              void* d_out, int out_size)
{
    const float* v       = (const float*)d_in[0];
    const float* q       = (const float*)d_in[1];
    const float* caption = (const float*)d_in[2];
    const int*   cap_len = (const int*)  d_in[3];
    const float* w_ih1   = (const float*)d_in[4];
    const float* w_hh1   = (const float*)d_in[5];
    const float* b_ih1   = (const float*)d_in[6];
    const float* b_hh1   = (const float*)d_in[7];
    const float* w_ih2   = (const float*)d_in[8];
    const float* w_hh2   = (const float*)d_in[9];
    const float* b_ih2   = (const float*)d_in[10];
    const float* b_hh2   = (const float*)d_in[11];
    const float* Wv      = (const float*)d_in[12];
    const float* Wq      = (const float*)d_in[13];
    const float* Wfc     = (const float*)d_in[14];

    float* out    = (float*)d_out;
    float* alphas = (float*)d_out + (size_t)BATCH * HD;

    float *fv, *fq, *fvq, *h1, *h2, *y;
    cudaGetSymbolAddress((void**)&fv,   g_fv);
    cudaGetSymbolAddress((void**)&fq,   g_fq);
    cudaGetSymbolAddress((void**)&fvq,  g_fvq);
    cudaGetSymbolAddress((void**)&h1,   g_h1);
    cudaGetSymbolAddress((void**)&h2,   g_h2);
    cudaGetSymbolAddress((void**)&y,    g_y);

    __half *gi1a, *gh1, *gi2a, *gh2;
    __half *c16s, *v16s, *q16s, *wih1h, *whh1h, *wih2h, *whh2h, *wvh, *wqh, *wfch;
    __half *h1h, *h2h, *atta, *h2ah;
    cudaGetSymbolAddress((void**)&gi1a,  g_gi1a);
    cudaGetSymbolAddress((void**)&gh1,   g_gh1);
    cudaGetSymbolAddress((void**)&gi2a,  g_gi2a);
    cudaGetSymbolAddress((void**)&gh2,   g_gh2);
    cudaGetSymbolAddress((void**)&c16s,  g_c16s);
    cudaGetSymbolAddress((void**)&v16s,  g_v16s);
    cudaGetSymbolAddress((void**)&q16s,  g_q16s);
    cudaGetSymbolAddress((void**)&wih1h, g_wih1h);
    cudaGetSymbolAddress((void**)&whh1h, g_whh1h);
    cudaGetSymbolAddress((void**)&wih2h, g_wih2h);
    cudaGetSymbolAddress((void**)&whh2h, g_whh2h);
    cudaGetSymbolAddress((void**)&wvh,   g_wvh);
    cudaGetSymbolAddress((void**)&wqh,   g_wqh);
    cudaGetSymbolAddress((void**)&wfch,  g_wfch);
    cudaGetSymbolAddress((void**)&h1h,   g_h1h);
    cudaGetSymbolAddress((void**)&h2h,   g_h2h);
    cudaGetSymbolAddress((void**)&atta,  g_atta);
    cudaGetSymbolAddress((void**)&h2ah,  g_h2ah);

    int *perm, *rankof, *mt;
    cudaGetSymbolAddress((void**)&perm,   g_perm);
    cudaGetSymbolAddress((void**)&rankof, g_rank);
    cudaGetSymbolAddress((void**)&mt,     g_mt);

    cudaFuncSetAttribute(h16_gemm_nt<float>,
                         cudaFuncAttributeMaxDynamicSharedMemorySize, SMEM_P);
    cudaFuncSetAttribute(h16_gemm_nt<__half>,
                         cudaFuncAttributeMaxDynamicSharedMemorySize, SMEM_P);

    // ---- one-time stream/event creation ----
    static cudaStream_t s1 = nullptr, s2 = nullptr, s3 = nullptr;
    static cudaEvent_t ePre, eCap, eFq, eW2, eY;
    static cudaEvent_t evG[TT], evA[TT], evB[TT], evC[TT];
    if (!s1) {
        int loPri, hiPri;
        cudaDeviceGetStreamPriorityRange(&loPri, &hiPri);
        cudaStreamCreateWithPriority(&s1, cudaStreamNonBlocking, hiPri);
        cudaStreamCreateWithPriority(&s2, cudaStreamNonBlocking, hiPri);
        cudaStreamCreateWithPriority(&s3, cudaStreamNonBlocking, loPri);
        cudaEventCreateWithFlags(&ePre, cudaEventDisableTiming);
        cudaEventCreateWithFlags(&eCap, cudaEventDisableTiming);
        cudaEventCreateWithFlags(&eFq,  cudaEventDisableTiming);
        cudaEventCreateWithFlags(&eW2,  cudaEventDisableTiming);
        cudaEventCreateWithFlags(&eY,   cudaEventDisableTiming);
        for (int i = 0; i < TT; i++) {
            cudaEventCreateWithFlags(&evG[i], cudaEventDisableTiming);
            cudaEventCreateWithFlags(&evA[i], cudaEventDisableTiming);
            cudaEventCreateWithFlags(&evB[i], cudaEventDisableTiming);
            cudaEventCreateWithFlags(&evC[i], cudaEventDisableTiming);
        }
    }

    const int EW = 256;

    // =================== shared prefix on main: sort metadata =====================
    rank_kernel<<<1, 1024>>>(cap_len, perm, rankof);
    mt_kernel<<<1, 32>>>(cap_len, mt);
    cudaEventRecord(ePre, 0);
    cudaStreamWaitEvent(s1, ePre, 0);
    cudaStreamWaitEvent(s2, ePre, 0);

    // =================== main: caption fp16 + wih1 cvt ============================
    f2h_kernel<<<(3 * CD * CD / 4 + EW - 1) / EW, EW>>>(w_ih1, wih1h, 3 * CD * CD);
    permcap_kernel<<<(TT * BATCH * (CD / 4) + EW - 1) / EW, EW>>>(caption, c16s, perm);
    cudaEventRecord(eCap, 0);
    cudaStreamWaitEvent(s3, eCap, 0);

    // =================== s3: per-step gi1 slabs ====================================
    for (int t = 0; t < TT; t++) {
        h16_gemm_nt<__half><<<gemm_grid(BATCH, 3 * CD), 256, SMEM_P, s3>>>(
            c16s + (size_t)t * BATCH * CD, wih1h, b_ih1,
            gi1a + (size_t)t * BATCH * 3 * CD,
            BATCH, 3 * CD, CD, 0, mt, t, 0);
        cudaEventRecord(evG[t], s3);
    }
    f2h_kernel<<<(HD * HD / 4 + EW - 1) / EW, EW, 0, s3>>>(Wfc, wfch, HD * HD);

    // =================== s2: fq GEMM + GRU2 weight cvts + h2 init =================
    f2h_kernel<<<(CD * QD / 4 + EW - 1) / EW, EW, 0, s2>>>(Wq, wqh, CD * QD);
    f2h_perm_kernel<<<(BATCH * (QD / 4) + EW - 1) / EW, EW, 0, s2>>>(q, q16s, perm, QD, BATCH);
    h16_gemm_nt<float><<<gemm_grid(BATCH, CD), 256, SMEM_P, s2>>>(
        q16s, wqh, nullptr, fq, BATCH, CD, QD, 1, nullptr, 0, 0);
    cudaEventRecord(eFq, s2);
    f2h_kernel<<<(3 * HD * CD / 4 + EW - 1) / EW, EW, 0, s2>>>(w_ih2, wih2h, 3 * HD * CD);
    cudaEventRecord(eW2, s2);
    f2h_kernel<<<(3 * HD * HD / 4 + EW - 1) / EW, EW, 0, s2>>>(w_hh2, whh2h, 3 * HD * HD);
    zero_state_kernel<<<(BATCH * HD + EW - 1) / EW, EW, 0, s2>>>(h2, h2h, BATCH * HD);

    // =================== s1: fv GEMM + fvq + h1 init + whh1 cvt ===================
    f2h_kernel<<<(3 * CD * CD / 4 + EW - 1) / EW, EW, 0, s1>>>(w_hh1, whh1h, 3 * CD * CD);
    f2h_kernel<<<(CD * VD / 4 + EW - 1) / EW, EW, 0, s1>>>(Wv, wvh, CD * VD);
    f2h_perm_kernel<<<(BATCH * (VD / 4) + EW - 1) / EW, EW, 0, s1>>>(v, v16s, perm, VD, BATCH);
    h16_gemm_nt<float><<<gemm_grid(BATCH, CD), 256, SMEM_P, s1>>>(
        v16s, wvh, nullptr, fv, BATCH, CD, VD, 1, nullptr, 0, 0);
    cudaStreamWaitEvent(s1, eFq, 0);
    add_kernel<<<(BATCH * CD + EW - 1) / EW, EW, 0, s1>>>(fv, fq, fvq, BATCH * CD);
    zero_state_kernel<<<(BATCH * CD + EW - 1) / EW, EW, 0, s1>>>(h1, h1h, BATCH * CD);

    // =================== s1: h1 recurrence chain ==================================
    // gh1(t) depends only on h1h (same-stream); gi1 slab is needed only by gru1.
    for (int t = 0; t < TT; t++) {
        h16_gemm_nt<__half><<<gemm_grid(BATCH, 3 * CD), 256, SMEM_P, s1>>>(
            h1h, whh1h, b_hh1, gh1, BATCH, 3 * CD, CD, 0, mt, t, 0);
        cudaStreamWaitEvent(s1, evG[t], 0);
        gru1_att_sorted<<<(BATCH * (CD / 2) + EW - 1) / EW, EW, 0, s1>>>(
            gi1a, gh1, caption, fvq, perm, mt, h1, h1h, atta, alphas, t);
        cudaEventRecord(evA[t], s1);
    }

    // =================== main: per-step gi2 slabs (after gru1(t), wih2h) ==========
    cudaStreamWaitEvent(0, eW2, 0);
    for (int t = 0; t < TT; t++) {
        cudaStreamWaitEvent(0, evA[t], 0);
        h16_gemm_nt<__half><<<gemm_grid(BATCH, 3 * HD), 256, SMEM_P>>>(
            atta + (size_t)t * BATCH * CD, wih2h, b_ih2,
            gi2a + (size_t)t * BATCH * 3 * HD,
            BATCH, 3 * HD, CD, 0, mt, t, 0);
        cudaEventRecord(evB[t], 0);
    }

    // =================== s2: h2 recurrence chain ==================================
    // gh2(t) depends only on h2h (same-stream); gi2 slab is needed only by gru2.
    // So gh2(t) runs CONCURRENT with gi2 slab(t) on main.
    for (int t = 0; t < TT; t++) {
        h16_gemm_nt<__half><<<gemm_grid(BATCH, 3 * HD), 256, SMEM_P, s2>>>(
            h2h, whh2h, b_hh2, gh2, BATCH, 3 * HD, HD, 0, mt, t, 0);
        cudaStreamWaitEvent(s2, evB[t], 0);
        gru2_sorted<<<(BATCH * (HD / 2) + EW - 1) / EW, EW, 0, s2>>>(
            gi2a, gh2, mt, h2, h2h, h2ah, t);
        cudaEventRecord(evC[t], s2);
    }

    // =================== s3: per-step Wfc slabs (after gru2(t)) ===================
    for (int t = 0; t < TT; t++) {
        cudaStreamWaitEvent(s3, evC[t], 0);
        h16_gemm_nt<float><<<gemm_grid(BATCH, HD), 256, SMEM_P, s3>>>(
            h2ah + (size_t)t * BATCH * HD, wfch, nullptr,
            y + (size_t)t * BATCH * HD,
            BATCH, HD, HD, 0, mt, t, 0);
    }
    cudaEventRecord(eY, s3);

    // =================== main: join + final reduction =============================
    cudaStreamWaitEvent(0, eY, 0);
    maxreduce_out<<<(BATCH * HD + EW - 1) / EW, EW>>>(y, cap_len, rankof, out);
}